// round 12
// baseline (speedup 1.0000x reference)
#include <cuda_runtime.h>
#include <stdint.h>

#define GRID_RES 64
#define BB 8
#define NN 4096
#define KC 55                         // 440 blocks ~ one 3-resident wave
#define CH 75                         // 55*75 = 4125 >= 4096
#define TILE 16
#define TTILES 5                      // 80 slots, pad -> mf=0 (zero contribution)
#define RF_STRIDE 66                  // 64 + 2; 264B/row (8B aligned row-pairs)
#define CFD_SEG 20                    // per-segment stride (16 used + 4 pad), 80B
#define CFD_STRIDE 168                // 8*20 + 8 pad; 672B/row (16B aligned)
#define SP_STRIDE 12                  // px,py,mf,pad,{y,y},{t,t}
#define PART_ELEMS (3 * 64 * 64)

// partials stored TRANSPOSED: [ch][col][row]
__device__ float g_partial[BB * KC * PART_ELEMS];

typedef unsigned long long u64;

__device__ __forceinline__ float ex2f(float x) {
    float r;
    asm("ex2.approx.f32 %0, %1;" : "=f"(r) : "f"(x));
    return r;
}

#define FMA2(d, a, b) asm("fma.rn.f32x2 %0, %1, %2, %0;" : "+l"(d) : "l"(a), "l"(b))
#define MUL2(d, a, b) asm("mul.rn.f32x2 %0, %1, %2;" : "=l"(d) : "l"(a), "l"(b))
#define PACK2(d, f)   asm("mov.b64 %0, {%1, %1};" : "=l"(d) : "f"(f))

__global__ __launch_bounds__(256, 3)
void rbf_partial_kernel(const float* __restrict__ xc,
                        const float* __restrict__ yc,
                        const float* __restrict__ tc,
                        const int* __restrict__ mask) {
    const int b = blockIdx.y;
    const int kc = blockIdx.x;
    const int tid = threadIdx.x;

    const float CEXP = -72.13475204444817f;  // L = -50 * log2(e)
    const float STEP = 2.0f / 63.0f;
    const float TK1 = CEXP * STEP * STEP;          // L*s^2
    const float TK2 = -2.0f * CEXP * STEP;         // -2*L*s
    const float C2 = ex2f(2.0f * CEXP * STEP * STEP); // 2^(2*L*s^2)

    __shared__ float sRF[2][TILE][RF_STRIDE];   // raw wy per row (dbl-buffered)
    __shared__ float sCFd[2][TILE][CFD_STRIDE]; // duplicated {wx*mf} pairs (dbl)
    __shared__ float sP[3][TILE][SP_STRIDE];    // TRIPLE-buffered: px,py,mf,-,{y,y},{t,t}
                                                // (stage B reads slot t%3 while
                                                //  STSP fills (t+2)%3 — disjoint)

    // stage-B: warp w = col-octave, lane = row-pair
    // acc[ch][c] = {out[ch][2l][8w+c], out[ch][2l+1][8w+c]}
    u64 acc[3][8];
#pragma unroll
    for (int ch = 0; ch < 3; ch++)
#pragma unroll
        for (int c = 0; c < 8; c++) acc[ch][c] = 0ULL;

    const int w = tid >> 5;
    const int lane = tid & 31;
    const int row0 = lane << 1;
    const int cfo = w * CFD_SEG;        // warp w reads its own segment

    // stage-A: thread = (point p4, segment s8, axis)
    const int p4 = tid >> 4;            // 0..15
    const int s8 = (tid >> 1) & 7;      // 0..7
    const int axisRF = ((tid & 1) == 0);
    const float gstart = -1.0f + STEP * (float)(s8 << 3);

    const int p0 = kc * CH;
    const int p1 = min(p0 + CH, NN);

    float Px = 0.f, Py = 0.f, Mf = 0.f, Yv = 0.f, Tv = 0.f;

#define LOADP(tt)                                                         \
    do {                                                                  \
        if (tid < TILE && (tt) < TTILES) {                                \
            const int n = p0 + (tt) * TILE + tid;                         \
            if (n < p1) {                                                 \
                Px = xc[(b * NN + n) * 2 + 0];                            \
                Py = xc[(b * NN + n) * 2 + 1];                            \
                Mf = (mask[b * NN + n] != 0) ? 0.0f : 1.0f;               \
                Yv = yc[b * NN + n];                                      \
                Tv = tc[b * NN + n];                                      \
            } else { Px = Py = Mf = Yv = Tv = 0.0f; }                     \
        }                                                                 \
    } while (0)

#define STSP(tt)                                                          \
    do {                                                                  \
        if (tid < TILE && (tt) < TTILES) {                                \
            const int sp_ = (tt) % 3;                                     \
            sP[sp_][tid][0] = Px; sP[sp_][tid][1] = Py;                   \
            sP[sp_][tid][2] = Mf;                                         \
            sP[sp_][tid][4] = Yv; sP[sp_][tid][5] = Yv;                   \
            sP[sp_][tid][6] = Tv; sP[sp_][tid][7] = Tv;                   \
        }                                                                 \
    } while (0)

// Recurrence: w_{j+1} = w_j * t_j, t_{j+1} = t_j * C2; 2 MUFU per thread total.
#define STAGE_A(tt)                                                       \
    do {                                                                  \
        const int bb_ = (tt) & 1;                                         \
        const int sp_ = (tt) % 3;                                         \
        if (axisRF) {                                                     \
            const float d0 = sP[sp_][p4][1] - gstart;                     \
            float wv = ex2f(CEXP * d0 * d0);                              \
            float tv = ex2f(TK1 + TK2 * d0);                              \
            _Pragma("unroll")                                             \
            for (int j = 0; j < 8; j++) {                                 \
                sRF[bb_][p4][(s8 << 3) + j] = wv;                         \
                wv *= tv; tv *= C2;                                       \
            }                                                             \
        } else {                                                          \
            const float d0 = sP[sp_][p4][0] - gstart;                     \
            float wv = ex2f(CEXP * d0 * d0) * sP[sp_][p4][2];  /* mf */   \
            float tv = ex2f(TK1 + TK2 * d0);                              \
            _Pragma("unroll")                                             \
            for (int j = 0; j < 8; j++) {                                 \
                u64 dd;                                                   \
                PACK2(dd, wv);                                            \
                *(u64*)&sCFd[bb_][p4][s8 * CFD_SEG + 2 * j] = dd;         \
                wv *= tv; tv *= C2;                                       \
            }                                                             \
        }                                                                 \
    } while (0)

#define STAGE_B(tt)                                                       \
    do {                                                                  \
        const int bb_ = (tt) & 1;                                         \
        const int sp_ = (tt) % 3;                                         \
        _Pragma("unroll 8")                                               \
        for (int p = 0; p < TILE; p++) {                                  \
            const float4* cf = (const float4*)&sCFd[bb_][p][cfo];         \
            const float4 f0 = cf[0];  /* broadcast across warp */         \
            const float4 f1 = cf[1];                                      \
            const float4 f2 = cf[2];                                      \
            const float4 f3 = cf[3];                                      \
            const u64* c01 = (const u64*)&f0;                             \
            const u64* c23 = (const u64*)&f1;                             \
            const u64* c45 = (const u64*)&f2;                             \
            const u64* c67 = (const u64*)&f3;                             \
            const u64 r0 = *(const u64*)&sRF[bb_][p][row0];  /* wy pair */\
            const u64 yp = *(const u64*)&sP[sp_][p][4];      /* {y,y} */  \
            const u64 tp = *(const u64*)&sP[sp_][p][6];      /* {t,t} */  \
            u64 r1, r2;                                                   \
            MUL2(r1, r0, yp);                                             \
            MUL2(r2, r0, tp);                                             \
            FMA2(acc[0][0], r0, c01[0]); FMA2(acc[0][1], r0, c01[1]);     \
            FMA2(acc[0][2], r0, c23[0]); FMA2(acc[0][3], r0, c23[1]);     \
            FMA2(acc[0][4], r0, c45[0]); FMA2(acc[0][5], r0, c45[1]);     \
            FMA2(acc[0][6], r0, c67[0]); FMA2(acc[0][7], r0, c67[1]);     \
            FMA2(acc[1][0], r1, c01[0]); FMA2(acc[1][1], r1, c01[1]);     \
            FMA2(acc[1][2], r1, c23[0]); FMA2(acc[1][3], r1, c23[1]);     \
            FMA2(acc[1][4], r1, c45[0]); FMA2(acc[1][5], r1, c45[1]);     \
            FMA2(acc[1][6], r1, c67[0]); FMA2(acc[1][7], r1, c67[1]);     \
            FMA2(acc[2][0], r2, c01[0]); FMA2(acc[2][1], r2, c01[1]);     \
            FMA2(acc[2][2], r2, c23[0]); FMA2(acc[2][3], r2, c23[1]);     \
            FMA2(acc[2][4], r2, c45[0]); FMA2(acc[2][5], r2, c45[1]);     \
            FMA2(acc[2][6], r2, c67[0]); FMA2(acc[2][7], r2, c67[1]);     \
        }                                                                 \
    } while (0)

    // prologue
    LOADP(0); STSP(0);
    LOADP(1); STSP(1);
    LOADP(2);
    __syncthreads();
    STAGE_A(0);
    __syncthreads();

#pragma unroll 1
    for (int t = 0; t < TTILES; t++) {
        STSP(t + 2);
        LOADP(t + 3);
        if (t + 1 < TTILES) STAGE_A(t + 1);
        STAGE_B(t);
        __syncthreads();
    }

    // epilogue into transposed partials [ch][col][row]: contiguous STG.64,
    // lanes cover rows 0..63 -> 256B coalesced per (ch,c).
    float* dst = &g_partial[(b * KC + kc) * PART_ELEMS];
#pragma unroll
    for (int ch = 0; ch < 3; ch++) {
#pragma unroll
        for (int c = 0; c < 8; c++) {
            *(u64*)&dst[ch * 4096 + (8 * w + c) * 64 + row0] = acc[ch][c];
        }
    }
}

// Fused finalize: one thread per (b, transposed cell); all 3 channels.
// Reads coalesced over gp; de-transposed scattered 4B writes (cheap).
__global__ __launch_bounds__(256)
void rbf_finalize_kernel(float* __restrict__ out) {
    const int idx = blockIdx.x * blockDim.x + threadIdx.x;  // 128*256 = 32768
    const int b = idx >> 12;
    const int gp = idx & 4095;          // gp = col*64 + row
    const int row = gp & 63;
    const int col = gp >> 6;

    const float* base = &g_partial[b * KC * PART_ELEMS] + gp;
    float s0 = 0.0f, s1 = 0.0f, s2 = 0.0f;
#pragma unroll
    for (int kcc = 0; kcc < KC; kcc++) {
        const float* pp = base + kcc * PART_ELEMS;
        s0 += pp[0];
        s1 += pp[4096];
        s2 += pp[8192];
    }
    const float inv = 1.0f / (s0 + 1e-5f);
    float* o = out + b * 12288 + row * 64 + col;
    o[0] = s0;
    o[4096] = s1 * inv;
    o[8192] = s2 * inv;
}

extern "C" void kernel_launch(void* const* d_in, const int* in_sizes, int n_in,
                              void* d_out, int out_size) {
    const float* xc = (const float*)d_in[0];
    const float* yc = (const float*)d_in[1];
    const float* tc = (const float*)d_in[2];
    const int* mask = (const int*)d_in[3];

    dim3 grid(KC, BB);
    rbf_partial_kernel<<<grid, 256>>>(xc, yc, tc, mask);

    rbf_finalize_kernel<<<128, 256>>>((float*)d_out);
}